// round 1
// baseline (speedup 1.0000x reference)
#include <cuda_runtime.h>
#include <cuda_bf16.h>

#define N_Q 16384
#define M_R 16384
#define DIM 16
#define JS  18          // j-slices (grid.y)
#define TJ  128         // js per smem tile
#define TPB 256
#define QPT 4           // queries per thread

// Scratch (no allocations allowed): c2 = {-0.5*||xb_j||^2, 0}, partial results.
__device__ unsigned long long g_c2[M_R];
__device__ float g_pbest[N_Q * JS];
__device__ int   g_pidx [N_Q * JS];

__device__ __forceinline__ unsigned long long ffma2(unsigned long long a,
                                                    unsigned long long b,
                                                    unsigned long long c) {
    unsigned long long d;
    asm("fma.rn.f32x2 %0, %1, %2, %3;" : "=l"(d) : "l"(a), "l"(b), "l"(c));
    return d;
}
__device__ __forceinline__ unsigned long long pack2(float lo, float hi) {
    unsigned long long d;
    asm("mov.b64 %0, {%1, %2};" : "=l"(d) : "f"(lo), "f"(hi));
    return d;
}
__device__ __forceinline__ void unpack2(unsigned long long v, float& lo, float& hi) {
    asm("mov.b64 {%0, %1}, %2;" : "=f"(lo), "=f"(hi) : "l"(v));
}

// Kernel 1: c_j = -0.5 * ||xb_j||^2, stored packed {c_j, 0.f}
__global__ void prep_kernel(const float* __restrict__ xb) {
    int j = blockIdx.x * blockDim.x + threadIdx.x;
    if (j >= M_R) return;
    const float4* r = (const float4*)(xb + (size_t)j * DIM);
    float s = 0.f;
#pragma unroll
    for (int i = 0; i < 4; i++) {
        float4 v = r[i];
        s += v.x * v.x + v.y * v.y + v.z * v.z + v.w * v.w;
    }
    g_c2[j] = pack2(-0.5f * s, 0.0f);
}

// Kernel 2: main scan. score_j = dot(x_q, xb_j) - 0.5*||xb_j||^2, argmax over slice.
__global__ __launch_bounds__(TPB, 2) void nn_kernel(const float* __restrict__ x,
                                                    const float* __restrict__ xb) {
    __shared__ float4 s_w[TJ * 4];                 // xb rows: 4 float4 per j
    __shared__ unsigned long long s_c[TJ];         // packed {c_j, 0}

    const int qb  = blockIdx.x;
    const int sl  = blockIdx.y;
    const int j0  = (sl * M_R) / JS;
    const int j1  = ((sl + 1) * M_R) / JS;
    const int tid = threadIdx.x;

    // Load QPT query rows, pack dims pairwise: xr[k][p] = {x[2p], x[2p+1]}
    unsigned long long xr[QPT][8];
    int qidx[QPT];
#pragma unroll
    for (int k = 0; k < QPT; k++) {
        int q = qb * (TPB * QPT) + k * TPB + tid;
        qidx[k] = q;
        const float4* r = (const float4*)(x + (size_t)q * DIM);
#pragma unroll
        for (int i = 0; i < 4; i++) {
            float4 v = r[i];
            xr[k][i * 2 + 0] = pack2(v.x, v.y);
            xr[k][i * 2 + 1] = pack2(v.z, v.w);
        }
    }

    float best[QPT];
    int   bidx[QPT];
#pragma unroll
    for (int k = 0; k < QPT; k++) { best[k] = -3.0e38f; bidx[k] = 0; }

    for (int jt = j0; jt < j1; jt += TJ) {
        int cnt = min(TJ, j1 - jt);
        __syncthreads();
        for (int t = tid; t < cnt * 4; t += TPB)
            s_w[t] = ((const float4*)xb)[jt * 4 + t];
        for (int t = tid; t < cnt; t += TPB)
            s_c[t] = g_c2[jt + t];
        __syncthreads();

        const ulonglong2* w2 = (const ulonglong2*)s_w;  // 4 ulonglong2 per j
        for (int jj = 0; jj < cnt; jj++) {
            ulonglong2 a0 = w2[jj * 4 + 0];
            ulonglong2 a1 = w2[jj * 4 + 1];
            ulonglong2 a2 = w2[jj * 4 + 2];
            ulonglong2 a3 = w2[jj * 4 + 3];
            unsigned long long ini = s_c[jj];
            int j = jt + jj;
#pragma unroll
            for (int k = 0; k < QPT; k++) {
                unsigned long long acc;
                acc = ffma2(xr[k][0], a0.x, ini);   // bias folded into first FMA
                acc = ffma2(xr[k][1], a0.y, acc);
                acc = ffma2(xr[k][2], a1.x, acc);
                acc = ffma2(xr[k][3], a1.y, acc);
                acc = ffma2(xr[k][4], a2.x, acc);
                acc = ffma2(xr[k][5], a2.y, acc);
                acc = ffma2(xr[k][6], a3.x, acc);
                acc = ffma2(xr[k][7], a3.y, acc);
                float lo, hi;
                unpack2(acc, lo, hi);
                float s = lo + hi;
                if (s > best[k]) { best[k] = s; bidx[k] = j; }
            }
        }
    }

#pragma unroll
    for (int k = 0; k < QPT; k++) {
        g_pbest[qidx[k] * JS + sl] = best[k];
        g_pidx [qidx[k] * JS + sl] = bidx[k];
    }
}

// Kernel 3: merge partials (ascending slice order + strict > == first-index argmin), gather y.
__global__ void merge_kernel(const float* __restrict__ y, float* __restrict__ out) {
    int q = blockIdx.x * blockDim.x + threadIdx.x;
    if (q >= N_Q) return;
    float best = -3.0e38f;
    int bi = 0;
#pragma unroll
    for (int p = 0; p < JS; p++) {
        float b = g_pbest[q * JS + p];
        int   i = g_pidx [q * JS + p];
        if (b > best) { best = b; bi = i; }
    }
    out[q] = y[bi];
}

extern "C" void kernel_launch(void* const* d_in, const int* in_sizes, int n_in,
                              void* d_out, int out_size) {
    const float* x  = (const float*)d_in[0];   // [16384,16]
    const float* xb = (const float*)d_in[1];   // [16384,16]
    const float* y  = (const float*)d_in[2];   // [16384]
    float* out = (float*)d_out;                // [16384]

    prep_kernel<<<M_R / 256, 256>>>(xb);
    dim3 grid(N_Q / (TPB * QPT), JS);          // (16, 18) = 288 CTAs
    nn_kernel<<<grid, TPB>>>(x, xb);
    merge_kernel<<<N_Q / 256, 256>>>(y, out);
}